// round 10
// baseline (speedup 1.0000x reference)
#include <cuda_runtime.h>
#include <cuda_fp16.h>
#include <cstdint>

#define NN 50000
#define NE 800000
#define DD 128
#define NB 196
#define BM 64
#define TOT_BLOCKS ((NN + BM - 1) / BM)   // 782
#define CSR_BLOCKS 592

// Scratch (__device__ globals; zero-init at load, invariants restored per run)
__device__ __half g_hh[NN * DD];
__device__ __half g_eh[16 * DD];
__device__ float  g_norm[NN];
__device__ int    g_cnt[NN];
__device__ int    g_rowptr[NN + 1];
__device__ int    g_cursor[NN];
__device__ int    g_bsum[256];
__device__ int    g_boff[256];
__device__ int    g_bar_count;
__device__ int    g_bar_gen;
__device__ int    g_edata[NE];

// ---------------- persistent CSR kernel ----------------
__device__ __forceinline__ void gridbar() {
    __syncthreads();
    if (threadIdx.x == 0) {
        __threadfence();
        int gen = *((volatile int*)&g_bar_gen);
        int t = atomicAdd(&g_bar_count, 1);
        if (t == CSR_BLOCKS - 1) {
            g_bar_count = 0;
            __threadfence();
            atomicAdd(&g_bar_gen, 1);
        } else {
            while (*((volatile int*)&g_bar_gen) == gen) { }
        }
        __threadfence();
    }
    __syncthreads();
}

__global__ void __launch_bounds__(256, 8)
k_csr(const int* __restrict__ src, const int* __restrict__ dst,
      const int* __restrict__ efeat, const float* __restrict__ eemb) {
    __shared__ int s[256];
    int tid = threadIdx.x;
    int gtid = blockIdx.x * 256 + tid;
    const int gstride = CSR_BLOCKS * 256;

    for (int i = gtid; i < 16 * DD; i += gstride) g_eh[i] = __float2half_rn(eemb[i]);
    for (int i = gtid; i < NE; i += gstride) atomicAdd(&g_cnt[dst[i]], 1);
    gridbar();

    if (blockIdx.x < NB) {
        int idx = blockIdx.x * 256 + tid;
        int v = (idx < NN) ? g_cnt[idx] : 0;
        s[tid] = v;
        __syncthreads();
        for (int off = 128; off > 0; off >>= 1) {
            if (tid < off) s[tid] += s[tid + off];
            __syncthreads();
        }
        if (tid == 0) g_bsum[blockIdx.x] = s[0];
    }
    gridbar();

    if (blockIdx.x == 0) {
        int v = (tid < NB) ? g_bsum[tid] : 0;
        s[tid] = v;
        __syncthreads();
        for (int off = 1; off < 256; off <<= 1) {
            int u = (tid >= off) ? s[tid - off] : 0;
            __syncthreads();
            s[tid] += u;
            __syncthreads();
        }
        if (tid < NB) g_boff[tid] = s[tid] - v;
        if (tid == NB - 1) g_rowptr[NN] = s[tid];
    }
    gridbar();

    if (blockIdx.x < NB) {
        int idx = blockIdx.x * 256 + tid;
        int v = (idx < NN) ? g_cnt[idx] : 0;
        s[tid] = v;
        __syncthreads();
        for (int off = 1; off < 256; off <<= 1) {
            int u = (tid >= off) ? s[tid - off] : 0;
            __syncthreads();
            s[tid] += u;
            __syncthreads();
        }
        if (idx < NN) {
            int rp = g_boff[blockIdx.x] + s[tid] - v;
            g_rowptr[idx] = rp;
            g_cursor[idx] = rp;
            g_norm[idx] = rsqrtf((float)v + 1.0f);
            g_cnt[idx] = 0;
        }
    }
    gridbar();

    for (int e = gtid; e < NE; e += gstride) {
        int d = dst[e];
        int pos = atomicAdd(&g_cursor[d], 1);
        g_edata[pos] = (src[e] << 4) | efeat[e];
    }
}

// ---------------- GEMM (node-range chunk) ----------------
// sAT[k][row] (pitch 68), sWt[k][d] (pitch 132). Inner loop: 3 LDS.128 + 32 FFMA.
#define SAT_PITCH 68
#define SWT_PITCH 132
#define GEMM_SMEM ((DD * SAT_PITCH + DD * SWT_PITCH) * 4)   // 102400

__global__ void __launch_bounds__(256, 2)
k_gemm(const float* __restrict__ nfeat, const float* __restrict__ W,
       const float* __restrict__ bias, int block_off) {
    extern __shared__ float sm[];
    float* sAT = sm;                      // [128][68]
    float* sWt = sm + DD * SAT_PITCH;     // [128][132]

    int tid = threadIdx.x;
    int tx = tid & 15;
    int ty = tid >> 4;
    int m0 = (block_off + blockIdx.x) * BM;

    // W[d][k] -> sWt[k][d], vectorized global reads
    {
        const float4* w4 = (const float4*)W;
        for (int i = tid; i < DD * 32; i += 256) {
            int d = i >> 5, q = i & 31;
            float4 v = w4[i];
            int k = q * 4;
            sWt[(k    ) * SWT_PITCH + d] = v.x;
            sWt[(k + 1) * SWT_PITCH + d] = v.y;
            sWt[(k + 2) * SWT_PITCH + d] = v.z;
            sWt[(k + 3) * SWT_PITCH + d] = v.w;
        }
    }
    // nfeat tile -> sAT transposed
    {
        const float4* nf4 = (const float4*)nfeat;
        for (int t = tid; t < BM * 32; t += 256) {
            int row = t >> 5, q = t & 31;
            int n = m0 + row;
            float4 v = make_float4(0.f, 0.f, 0.f, 0.f);
            if (n < NN) v = nf4[n * 32 + q];
            int k = q * 4;
            sAT[(k    ) * SAT_PITCH + row] = v.x;
            sAT[(k + 1) * SAT_PITCH + row] = v.y;
            sAT[(k + 2) * SAT_PITCH + row] = v.z;
            sAT[(k + 3) * SAT_PITCH + row] = v.w;
        }
    }
    __syncthreads();

    float acc[4][8];
    #pragma unroll
    for (int i = 0; i < 4; i++)
        #pragma unroll
        for (int j = 0; j < 8; j++) acc[i][j] = 0.f;

    #pragma unroll 4
    for (int kk = 0; kk < DD; kk++) {
        float4 a4 = *(const float4*)(sAT + kk * SAT_PITCH + ty * 4);
        float4 w0 = *(const float4*)(sWt + kk * SWT_PITCH + tx * 8);
        float4 w1 = *(const float4*)(sWt + kk * SWT_PITCH + tx * 8 + 4);
        float a[4] = {a4.x, a4.y, a4.z, a4.w};
        float w[8] = {w0.x, w0.y, w0.z, w0.w, w1.x, w1.y, w1.z, w1.w};
        #pragma unroll
        for (int i = 0; i < 4; i++)
            #pragma unroll
            for (int j = 0; j < 8; j++)
                acc[i][j] = fmaf(a[i], w[j], acc[i][j]);
    }

    float4 b0 = ((const float4*)bias)[tx * 2];
    float4 b1 = ((const float4*)bias)[tx * 2 + 1];
    #pragma unroll
    for (int i = 0; i < 4; i++) {
        int n = m0 + ty * 4 + i;
        if (n >= NN) continue;
        __half2 h0 = __floats2half2_rn(acc[i][0] + b0.x, acc[i][1] + b0.y);
        __half2 h1 = __floats2half2_rn(acc[i][2] + b0.z, acc[i][3] + b0.w);
        __half2 h2 = __floats2half2_rn(acc[i][4] + b1.x, acc[i][5] + b1.y);
        __half2 h3 = __floats2half2_rn(acc[i][6] + b1.z, acc[i][7] + b1.w);
        uint4 pk = make_uint4(*(uint32_t*)&h0, *(uint32_t*)&h1,
                              *(uint32_t*)&h2, *(uint32_t*)&h3);
        *(uint4*)(g_hh + n * DD + tx * 8) = pk;
    }
}

// ---------------- aggregation: warp/node, half2 math ----------------
__global__ void __launch_bounds__(512, 4)
k_agg(const float* __restrict__ res_w, float* __restrict__ out) {
    __shared__ __half sE[16 * DD];
    int tid = threadIdx.x;
    for (int i = tid; i < 16 * DD / 2; i += 512)
        ((uint32_t*)sE)[i] = ((const uint32_t*)g_eh)[i];
    __syncthreads();

    int n = (blockIdx.x * 512 + tid) >> 5;
    if (n >= NN) return;
    int lane = tid & 31;

    int i   = g_rowptr[n];
    int end = g_rowptr[n + 1];

    const __half2 z2 = __float2half2_rn(0.f);
    float4 acc = make_float4(0.f, 0.f, 0.f, 0.f);

    if (i < end) {
        int p = g_edata[i];
        int s = p >> 4, t = p & 15;
        float ns = g_norm[s];
        uint2 rh = ((const uint2*)(g_hh + s * DD))[lane];
        uint2 re = ((const uint2*)(sE + t * DD))[lane];
        for (++i; i < end; ++i) {
            int p2 = g_edata[i];
            int s2 = p2 >> 4, t2 = p2 & 15;
            float ns2 = g_norm[s2];
            uint2 rh2 = ((const uint2*)(g_hh + s2 * DD))[lane];
            uint2 re2 = ((const uint2*)(sE + t2 * DD))[lane];
            __half2 v01 = __hmax2(__hadd2(*(__half2*)&rh.x, *(__half2*)&re.x), z2);
            __half2 v23 = __hmax2(__hadd2(*(__half2*)&rh.y, *(__half2*)&re.y), z2);
            float2 f01 = __half22float2(v01);
            float2 f23 = __half22float2(v23);
            acc.x = fmaf(ns, f01.x, acc.x);
            acc.y = fmaf(ns, f01.y, acc.y);
            acc.z = fmaf(ns, f23.x, acc.z);
            acc.w = fmaf(ns, f23.y, acc.w);
            rh = rh2; re = re2; ns = ns2;
        }
        __half2 v01 = __hmax2(__hadd2(*(__half2*)&rh.x, *(__half2*)&re.x), z2);
        __half2 v23 = __hmax2(__hadd2(*(__half2*)&rh.y, *(__half2*)&re.y), z2);
        float2 f01 = __half22float2(v01);
        float2 f23 = __half22float2(v23);
        acc.x = fmaf(ns, f01.x, acc.x);
        acc.y = fmaf(ns, f01.y, acc.y);
        acc.z = fmaf(ns, f23.x, acc.z);
        acc.w = fmaf(ns, f23.y, acc.w);
    }

    float nd = g_norm[n];
    float invd = nd * nd;
    uint2 rh = ((const uint2*)(g_hh + n * DD))[lane];
    float2 h01 = __half22float2(*(__half2*)&rh.x);
    float2 h23 = __half22float2(*(__half2*)&rh.y);
    float4 rw = ((const float4*)res_w)[lane];
    float4 o;
    o.x = nd * acc.x + invd * fmaxf(h01.x + rw.x, 0.f);
    o.y = nd * acc.y + invd * fmaxf(h01.y + rw.y, 0.f);
    o.z = nd * acc.z + invd * fmaxf(h23.x + rw.z, 0.f);
    o.w = nd * acc.w + invd * fmaxf(h23.y + rw.w, 0.f);
    ((float4*)(out + n * DD))[lane] = o;
}

extern "C" void kernel_launch(void* const* d_in, const int* in_sizes, int n_in,
                              void* d_out, int out_size) {
    const float* nfeat = (const float*)d_in[0];
    const int*   efeat = (const int*)d_in[1];
    const int*   src   = (const int*)d_in[2];
    const int*   dst   = (const int*)d_in[3];
    const float* W     = (const float*)d_in[4];
    const float* bias  = (const float*)d_in[5];
    const float* eemb  = (const float*)d_in[6];
    const float* res_w = (const float*)d_in[7];
    float* out = (float*)d_out;

    static cudaStream_t sA = nullptr, sB = nullptr;
    static cudaEvent_t evF = nullptr, evA = nullptr, evB = nullptr;
    if (!sA) {
        cudaStreamCreateWithFlags(&sA, cudaStreamNonBlocking);
        cudaStreamCreateWithFlags(&sB, cudaStreamNonBlocking);
        cudaEventCreateWithFlags(&evF, cudaEventDisableTiming);
        cudaEventCreateWithFlags(&evA, cudaEventDisableTiming);
        cudaEventCreateWithFlags(&evB, cudaEventDisableTiming);
        cudaFuncSetAttribute(k_gemm, cudaFuncAttributeMaxDynamicSharedMemorySize, GEMM_SMEM);
    }

    cudaEventRecord(evF, 0);
    cudaStreamWaitEvent(sA, evF, 0);
    cudaStreamWaitEvent(sB, evF, 0);

    // #1: CSR chain (persistent) on sB
    k_csr<<<CSR_BLOCKS, 256, 0, sB>>>(src, dst, efeat, eemb);
    cudaEventRecord(evB, sB);

    // #2..#4: GEMM in 3 node-range chunks on sA (#4 = gC gets profiled)
    const int C0 = 261, C1 = 261, C2 = TOT_BLOCKS - 522;   // 260
    k_gemm<<<C0, 256, GEMM_SMEM, sA>>>(nfeat, W, bias, 0);
    k_gemm<<<C1, 256, GEMM_SMEM, sA>>>(nfeat, W, bias, 261);
    k_gemm<<<C2, 256, GEMM_SMEM, sA>>>(nfeat, W, bias, 522);
    cudaEventRecord(evA, sA);

    // #5: join + aggregate
    cudaStreamWaitEvent(0, evA, 0);
    cudaStreamWaitEvent(0, evB, 0);
    k_agg<<<(NN * 32 + 511) / 512, 512>>>(res_w, out);
}

// round 13
// speedup vs baseline: 1.3755x; 1.3755x over previous
#include <cuda_runtime.h>
#include <cuda_fp16.h>
#include <cstdint>

#define NN 50000
#define NE 800000
#define DD 128
#define NB 196
#define CSR_BLOCKS 592
#define GB 128                              // GEMM node tile
#define GEMM_BLOCKS ((NN + GB - 1) / GB)    // 391

// Scratch (__device__ globals; zero-init at load, invariants restored per run)
__device__ __half g_hh[NN * DD];
__device__ __half g_eh[16 * DD];
__device__ float  g_norm[NN];
__device__ int    g_cnt[NN];
__device__ int    g_rowptr[NN + 1];
__device__ int    g_cursor[NN];
__device__ int    g_bsum[256];
__device__ int    g_boff[256];
__device__ int    g_bar_count;
__device__ int    g_bar_gen;
__device__ int    g_edata[NE];

// ---------------- persistent CSR kernel ----------------
__device__ __forceinline__ void gridbar() {
    __syncthreads();
    if (threadIdx.x == 0) {
        __threadfence();
        int gen = *((volatile int*)&g_bar_gen);
        int t = atomicAdd(&g_bar_count, 1);
        if (t == CSR_BLOCKS - 1) {
            g_bar_count = 0;
            __threadfence();
            atomicAdd(&g_bar_gen, 1);
        } else {
            while (*((volatile int*)&g_bar_gen) == gen) { }
        }
        __threadfence();
    }
    __syncthreads();
}

__global__ void __launch_bounds__(256, 8)
k_csr(const int* __restrict__ src, const int* __restrict__ dst,
      const int* __restrict__ efeat, const float* __restrict__ eemb) {
    __shared__ int s[256];
    int tid = threadIdx.x;
    int gtid = blockIdx.x * 256 + tid;
    const int gstride = CSR_BLOCKS * 256;

    for (int i = gtid; i < 16 * DD; i += gstride) g_eh[i] = __float2half_rn(eemb[i]);
    for (int i = gtid; i < NE; i += gstride) atomicAdd(&g_cnt[dst[i]], 1);
    gridbar();

    if (blockIdx.x < NB) {
        int idx = blockIdx.x * 256 + tid;
        int v = (idx < NN) ? g_cnt[idx] : 0;
        s[tid] = v;
        __syncthreads();
        for (int off = 128; off > 0; off >>= 1) {
            if (tid < off) s[tid] += s[tid + off];
            __syncthreads();
        }
        if (tid == 0) g_bsum[blockIdx.x] = s[0];
    }
    gridbar();

    if (blockIdx.x == 0) {
        int v = (tid < NB) ? g_bsum[tid] : 0;
        s[tid] = v;
        __syncthreads();
        for (int off = 1; off < 256; off <<= 1) {
            int u = (tid >= off) ? s[tid - off] : 0;
            __syncthreads();
            s[tid] += u;
            __syncthreads();
        }
        if (tid < NB) g_boff[tid] = s[tid] - v;
        if (tid == NB - 1) g_rowptr[NN] = s[tid];
    }
    gridbar();

    if (blockIdx.x < NB) {
        int idx = blockIdx.x * 256 + tid;
        int v = (idx < NN) ? g_cnt[idx] : 0;
        s[tid] = v;
        __syncthreads();
        for (int off = 1; off < 256; off <<= 1) {
            int u = (tid >= off) ? s[tid - off] : 0;
            __syncthreads();
            s[tid] += u;
            __syncthreads();
        }
        if (idx < NN) {
            int rp = g_boff[blockIdx.x] + s[tid] - v;
            g_rowptr[idx] = rp;
            g_cursor[idx] = rp;
            g_norm[idx] = rsqrtf((float)v + 1.0f);
            g_cnt[idx] = 0;
        }
    }
    gridbar();

    for (int e = gtid; e < NE; e += gstride) {
        int d = dst[e];
        int pos = atomicAdd(&g_cursor[d], 1);
        g_edata[pos] = (src[e] << 4) | efeat[e];
    }
}

// ---------------- GEMM: 128x128 tile, 8x8 per thread ----------------
// h[m][d] = sum_k nfeat[m][k] * W[d][k] + b[d]  -> g_hh fp16
// smem k-major: sA[k][row], sW[k][d], pitch 132 floats.
#define GP 132
#define GEMM_SMEM (2 * DD * GP * 4)    // 135168 B -> 1 CTA/SM

__global__ void __launch_bounds__(256, 1)
k_gemm(const float* __restrict__ nfeat, const float* __restrict__ W,
       const float* __restrict__ bias) {
    extern __shared__ float sm[];
    float* sA = sm;             // [128 k][132]
    float* sW = sm + DD * GP;   // [128 k][132]

    int tid = threadIdx.x;
    int tx = tid & 15;          // d-group: d = tx*8..+7
    int ty = tid >> 4;          // m-group: m = ty*8..+7
    int m0 = blockIdx.x * GB;

    // Fill: thread group of 32 lanes reads one row (coalesced, lane = k-chunk),
    // each thread handles 4 consecutive rows -> STS.128 along the row dim.
    // Thread i: rows r0 = (i>>5)*4 .. +3 of this 128-row band; k = (i&31)*4.
    {
        int lane = tid & 31;
        int grp  = tid >> 5;            // 0..7
        int k4 = lane * 4;              // k .. k+3
        for (int rb = grp * 16; rb < grp * 16 + 16; rb += 4) {
            // W rows rb..rb+3 (d index), k4..k4+3
            float4 w0 = *(const float4*)(W + (rb + 0) * DD + k4);
            float4 w1 = *(const float4*)(W + (rb + 1) * DD + k4);
            float4 w2 = *(const float4*)(W + (rb + 2) * DD + k4);
            float4 w3 = *(const float4*)(W + (rb + 3) * DD + k4);
            *(float4*)(sW + (k4 + 0) * GP + rb) = make_float4(w0.x, w1.x, w2.x, w3.x);
            *(float4*)(sW + (k4 + 1) * GP + rb) = make_float4(w0.y, w1.y, w2.y, w3.y);
            *(float4*)(sW + (k4 + 2) * GP + rb) = make_float4(w0.z, w1.z, w2.z, w3.z);
            *(float4*)(sW + (k4 + 3) * GP + rb) = make_float4(w0.w, w1.w, w2.w, w3.w);

            // nfeat rows m0+rb..+3
            float4 a0 = make_float4(0.f,0.f,0.f,0.f), a1 = a0, a2 = a0, a3 = a0;
            if (m0 + rb + 0 < NN) a0 = *(const float4*)(nfeat + (m0 + rb + 0) * DD + k4);
            if (m0 + rb + 1 < NN) a1 = *(const float4*)(nfeat + (m0 + rb + 1) * DD + k4);
            if (m0 + rb + 2 < NN) a2 = *(const float4*)(nfeat + (m0 + rb + 2) * DD + k4);
            if (m0 + rb + 3 < NN) a3 = *(const float4*)(nfeat + (m0 + rb + 3) * DD + k4);
            *(float4*)(sA + (k4 + 0) * GP + rb) = make_float4(a0.x, a1.x, a2.x, a3.x);
            *(float4*)(sA + (k4 + 1) * GP + rb) = make_float4(a0.y, a1.y, a2.y, a3.y);
            *(float4*)(sA + (k4 + 2) * GP + rb) = make_float4(a0.z, a1.z, a2.z, a3.z);
            *(float4*)(sA + (k4 + 3) * GP + rb) = make_float4(a0.w, a1.w, a2.w, a3.w);
        }
    }
    __syncthreads();

    float acc[8][8];
    #pragma unroll
    for (int i = 0; i < 8; i++)
        #pragma unroll
        for (int j = 0; j < 8; j++) acc[i][j] = 0.f;

    #pragma unroll 4
    for (int kk = 0; kk < DD; kk++) {
        const float* ak = sA + kk * GP + ty * 8;
        const float* wk = sW + kk * GP + tx * 8;
        float4 a0 = *(const float4*)(ak);
        float4 a1 = *(const float4*)(ak + 4);
        float4 w0 = *(const float4*)(wk);
        float4 w1 = *(const float4*)(wk + 4);
        float a[8] = {a0.x, a0.y, a0.z, a0.w, a1.x, a1.y, a1.z, a1.w};
        float w[8] = {w0.x, w0.y, w0.z, w0.w, w1.x, w1.y, w1.z, w1.w};
        #pragma unroll
        for (int i = 0; i < 8; i++)
            #pragma unroll
            for (int j = 0; j < 8; j++)
                acc[i][j] = fmaf(a[i], w[j], acc[i][j]);
    }

    // Epilogue: +bias, fp16, one uint4 per row
    float4 b0 = ((const float4*)bias)[tx * 2];
    float4 b1 = ((const float4*)bias)[tx * 2 + 1];
    #pragma unroll
    for (int i = 0; i < 8; i++) {
        int n = m0 + ty * 8 + i;
        if (n >= NN) continue;
        __half2 h0 = __floats2half2_rn(acc[i][0] + b0.x, acc[i][1] + b0.y);
        __half2 h1 = __floats2half2_rn(acc[i][2] + b0.z, acc[i][3] + b0.w);
        __half2 h2 = __floats2half2_rn(acc[i][4] + b1.x, acc[i][5] + b1.y);
        __half2 h3 = __floats2half2_rn(acc[i][6] + b1.z, acc[i][7] + b1.w);
        uint4 pk = make_uint4(*(uint32_t*)&h0, *(uint32_t*)&h1,
                              *(uint32_t*)&h2, *(uint32_t*)&h3);
        *(uint4*)(g_hh + n * DD + tx * 8) = pk;
    }
}

// ---------------- aggregation (R7 shape: warp/node, scalar fp32 math) ----------------
__global__ void __launch_bounds__(512, 4)
k_agg(const float* __restrict__ res_w, float* __restrict__ out) {
    __shared__ __half sE[16 * DD];
    int tid = threadIdx.x;
    for (int i = tid; i < 16 * DD / 2; i += 512)
        ((uint32_t*)sE)[i] = ((const uint32_t*)g_eh)[i];
    __syncthreads();

    int n = (blockIdx.x * 512 + tid) >> 5;
    if (n >= NN) return;
    int lane = tid & 31;

    int i   = g_rowptr[n];
    int end = g_rowptr[n + 1];

    float4 acc = make_float4(0.f, 0.f, 0.f, 0.f);
    if (i < end) {
        int p = g_edata[i];
        int s = p >> 4, t = p & 15;
        float ns = g_norm[s];
        uint2 rh = ((const uint2*)(g_hh + s * DD))[lane];
        uint2 re = ((const uint2*)(sE + t * DD))[lane];
        for (++i; i < end; ++i) {
            int p2 = g_edata[i];
            int s2 = p2 >> 4, t2 = p2 & 15;
            float ns2 = g_norm[s2];
            uint2 rh2 = ((const uint2*)(g_hh + s2 * DD))[lane];
            uint2 re2 = ((const uint2*)(sE + t2 * DD))[lane];
            float2 f01 = __half22float2(*(__half2*)&rh.x);
            float2 f23 = __half22float2(*(__half2*)&rh.y);
            float2 e01 = __half22float2(*(__half2*)&re.x);
            float2 e23 = __half22float2(*(__half2*)&re.y);
            acc.x += ns * fmaxf(f01.x + e01.x, 0.f);
            acc.y += ns * fmaxf(f01.y + e01.y, 0.f);
            acc.z += ns * fmaxf(f23.x + e23.x, 0.f);
            acc.w += ns * fmaxf(f23.y + e23.y, 0.f);
            rh = rh2; re = re2; ns = ns2;
        }
        float2 f01 = __half22float2(*(__half2*)&rh.x);
        float2 f23 = __half22float2(*(__half2*)&rh.y);
        float2 e01 = __half22float2(*(__half2*)&re.x);
        float2 e23 = __half22float2(*(__half2*)&re.y);
        acc.x += ns * fmaxf(f01.x + e01.x, 0.f);
        acc.y += ns * fmaxf(f01.y + e01.y, 0.f);
        acc.z += ns * fmaxf(f23.x + e23.x, 0.f);
        acc.w += ns * fmaxf(f23.y + e23.y, 0.f);
    }

    float nd = g_norm[n];
    float invd = nd * nd;
    uint2 rh = ((const uint2*)(g_hh + n * DD))[lane];
    float2 h01 = __half22float2(*(__half2*)&rh.x);
    float2 h23 = __half22float2(*(__half2*)&rh.y);
    float4 rw = ((const float4*)res_w)[lane];
    float4 o;
    o.x = nd * acc.x + invd * fmaxf(h01.x + rw.x, 0.f);
    o.y = nd * acc.y + invd * fmaxf(h01.y + rw.y, 0.f);
    o.z = nd * acc.z + invd * fmaxf(h23.x + rw.z, 0.f);
    o.w = nd * acc.w + invd * fmaxf(h23.y + rw.w, 0.f);
    ((float4*)(out + n * DD))[lane] = o;
}

extern "C" void kernel_launch(void* const* d_in, const int* in_sizes, int n_in,
                              void* d_out, int out_size) {
    const float* nfeat = (const float*)d_in[0];
    const int*   efeat = (const int*)d_in[1];
    const int*   src   = (const int*)d_in[2];
    const int*   dst   = (const int*)d_in[3];
    const float* W     = (const float*)d_in[4];
    const float* bias  = (const float*)d_in[5];
    const float* eemb  = (const float*)d_in[6];
    const float* res_w = (const float*)d_in[7];
    float* out = (float*)d_out;

    static cudaStream_t sA = nullptr, sB = nullptr;
    static cudaEvent_t evF = nullptr, evA = nullptr, evB = nullptr;
    if (!sA) {
        cudaStreamCreateWithFlags(&sA, cudaStreamNonBlocking);
        cudaStreamCreateWithFlags(&sB, cudaStreamNonBlocking);
        cudaEventCreateWithFlags(&evF, cudaEventDisableTiming);
        cudaEventCreateWithFlags(&evA, cudaEventDisableTiming);
        cudaEventCreateWithFlags(&evB, cudaEventDisableTiming);
        cudaFuncSetAttribute(k_gemm, cudaFuncAttributeMaxDynamicSharedMemorySize, GEMM_SMEM);
    }

    cudaEventRecord(evF, 0);
    cudaStreamWaitEvent(sA, evF, 0);
    cudaStreamWaitEvent(sB, evF, 0);

    // #1: CSR (persistent) on sB
    k_csr<<<CSR_BLOCKS, 256, 0, sB>>>(src, dst, efeat, eemb);
    cudaEventRecord(evB, sB);

    // #2: GEMM on sA (single launch)
    k_gemm<<<GEMM_BLOCKS, 256, GEMM_SMEM, sA>>>(nfeat, W, bias);
    cudaEventRecord(evA, sA);

    // #3: join + aggregate
    cudaStreamWaitEvent(0, evA, 0);
    cudaStreamWaitEvent(0, evB, 0);
    k_agg<<<(NN * 32 + 511) / 512, 512>>>(res_w, out);
}